// round 15
// baseline (speedup 1.0000x reference)
#include <cuda_runtime.h>
#include <math.h>

// Blur_22754736735026: upfirdn2d, UP=2, DOWN=1, 4x4 kernel, pad (1,2).
// imgs: (16,128,128,128) f32 NCHW -> out: (16,128,255,255) f32.
//
// out(2i+py, 2j+px) = 2x2 weighted sum of in(i..i+1, j..j+1):
//   even out rows: kernel rows 1,3 ; odd rows: kernel rows 0,2
//   even out cols: kernel cols 1,3 ; odd cols: kernel cols 0,2
// Odd output row 2i+1 exists iff i < 127 (OH=255).
//
// FINAL (R11/R13 winner, confirmed over 14 rounds): warp task = 2 input rows
// (3 front-batched LDG.128), two smem-staged pairs (STS.128), coalesced
// scalar __stcs drain (pitch 255 forbids vector stores), launch_bounds(256,7).
// Measured: 103.5 us bench / 101.4 us ncu, DRAM 75.6%, 5994 GB/s — at the
// write-dominant HBM wall (compulsory traffic ~667 MB).

#define HB   128
#define WB   128

// ---------------- specialized: shapes known -----------
__global__ __launch_bounds__(256, 7)
void blur_spec6(const float4* __restrict__ in4,
                const float4* __restrict__ ker4,
                float* __restrict__ out)
{
    __shared__ float sm[8][2][256];

    const int lane = threadIdx.x & 31;
    const int w    = threadIdx.x >> 5;
    const unsigned task = blockIdx.x * 8u + w;     // 131072 tasks
    const unsigned t    = task & 63u;              // row-pair index in plane
    const unsigned img  = task >> 6;
    const unsigned i0   = 2u * t;

    float kw[16];
    {
        const float4 a = __ldg(ker4 + 0), b = __ldg(ker4 + 1),
                     c = __ldg(ker4 + 2), d = __ldg(ker4 + 3);
        kw[ 0]=a.x; kw[ 1]=a.y; kw[ 2]=a.z; kw[ 3]=a.w;
        kw[ 4]=b.x; kw[ 5]=b.y; kw[ 6]=b.z; kw[ 7]=b.w;
        kw[ 8]=c.x; kw[ 9]=c.y; kw[10]=c.z; kw[11]=c.w;
        kw[12]=d.x; kw[13]=d.y; kw[14]=d.z; kw[15]=d.w;
    }

    const unsigned rowbase = (img * HB + i0) * 32u + lane;
    const bool lastpair = (t == 63u);              // warp-uniform

    float4 r0 = in4[rowbase];
    float4 r1 = in4[rowbase + 32u];
    float4 r2 = make_float4(0.f, 0.f, 0.f, 0.f);
    if (!lastpair) r2 = in4[rowbase + 64u];

    float n0 = __shfl_down_sync(0xffffffffu, r0.x, 1);
    float n1 = __shfl_down_sync(0xffffffffu, r1.x, 1);
    float n2 = __shfl_down_sync(0xffffffffu, r2.x, 1);
    if (lane == 31) { n0 = 0.f; n1 = 0.f; n2 = 0.f; }

    float* s0 = &sm[w][0][0];
    float* s1 = &sm[w][1][0];
    const unsigned g0A = img * 65025u + i0 * 510u;

    // ---- pair A: rows i0,i0+1 -> out rows 2i0, 2i0+1 (both exist) ----
    {
        const float ta[5] = { r0.x, r0.y, r0.z, r0.w, n0 };
        const float tb[5] = { r1.x, r1.y, r1.z, r1.w, n1 };
        float ev[8], od[8];
        #pragma unroll
        for (int u = 0; u < 4; ++u) {
            const float A = ta[u], B = ta[u+1], Cv = tb[u], D = tb[u+1];
            ev[2*u+0] = kw[5]*A + kw[7]*B + kw[13]*Cv + kw[15]*D;
            ev[2*u+1] = kw[4]*A + kw[6]*B + kw[12]*Cv + kw[14]*D;
            od[2*u+0] = kw[1]*A + kw[3]*B + kw[ 9]*Cv + kw[11]*D;
            od[2*u+1] = kw[0]*A + kw[2]*B + kw[ 8]*Cv + kw[10]*D;
        }
        ((float4*)s0)[2*lane    ] = make_float4(ev[0], ev[1], ev[2], ev[3]);
        ((float4*)s0)[2*lane + 1] = make_float4(ev[4], ev[5], ev[6], ev[7]);
        ((float4*)s1)[2*lane    ] = make_float4(od[0], od[1], od[2], od[3]);
        ((float4*)s1)[2*lane + 1] = make_float4(od[4], od[5], od[6], od[7]);
        __syncwarp();

        const unsigned o0 = g0A;
        const unsigned o1 = g0A + 255u;
        #pragma unroll
        for (int u = 0; u < 8; ++u) {
            const int c = lane + 32*u;
            if (u < 7 || lane < 31) {              // c < 255
                __stcs(out + o0 + c, s0[c]);
                __stcs(out + o1 + c, s1[c]);
            }
        }
        __syncwarp();                              // WAR: drain A before stage B
    }

    // ---- pair B: rows i0+1,i0+2 -> out rows 2i0+2, 2i0+3 ----
    {
        const float ta[5] = { r1.x, r1.y, r1.z, r1.w, n1 };
        const float tb[5] = { r2.x, r2.y, r2.z, r2.w, n2 };
        float ev[8], od[8];
        #pragma unroll
        for (int u = 0; u < 4; ++u) {
            const float A = ta[u], B = ta[u+1], Cv = tb[u], D = tb[u+1];
            ev[2*u+0] = kw[5]*A + kw[7]*B + kw[13]*Cv + kw[15]*D;
            ev[2*u+1] = kw[4]*A + kw[6]*B + kw[12]*Cv + kw[14]*D;
            od[2*u+0] = kw[1]*A + kw[3]*B + kw[ 9]*Cv + kw[11]*D;
            od[2*u+1] = kw[0]*A + kw[2]*B + kw[ 8]*Cv + kw[10]*D;
        }
        ((float4*)s0)[2*lane    ] = make_float4(ev[0], ev[1], ev[2], ev[3]);
        ((float4*)s0)[2*lane + 1] = make_float4(ev[4], ev[5], ev[6], ev[7]);
        ((float4*)s1)[2*lane    ] = make_float4(od[0], od[1], od[2], od[3]);
        ((float4*)s1)[2*lane + 1] = make_float4(od[4], od[5], od[6], od[7]);
        __syncwarp();

        const unsigned o0 = g0A + 510u;
        const unsigned o1 = o0 + 255u;
        #pragma unroll
        for (int u = 0; u < 8; ++u) {
            const int c = lane + 32*u;
            if (u < 7 || lane < 31) {              // c < 255
                __stcs(out + o0 + c, s0[c]);
                if (!lastpair) __stcs(out + o1 + c, s1[c]);
            }
        }
    }
}

// ---------------- generic guarded fallback (any shape) ----------------------
__global__ __launch_bounds__(256)
void blur_generic(const float* __restrict__ in,
                  const float* __restrict__ ker,
                  float* __restrict__ out,
                  int ntask, long long n_in_elems,
                  int OH, int OW, long long n_out_elems)
{
    __shared__ float sm[8][2][256];

    const int lane = threadIdx.x & 31;
    const int w    = threadIdx.x >> 5;
    const int task = blockIdx.x * 8 + w;
    if (task >= ntask) return;
    const int i    = task & (HB - 1);
    const int img  = task >> 7;

    float k00,k01,k02,k03,k10,k11,k12,k13,k20,k21,k22,k23,k30,k31,k32,k33;
    if (ker != nullptr) {
        k00 = __ldg(ker+ 0); k01 = __ldg(ker+ 1); k02 = __ldg(ker+ 2); k03 = __ldg(ker+ 3);
        k10 = __ldg(ker+ 4); k11 = __ldg(ker+ 5); k12 = __ldg(ker+ 6); k13 = __ldg(ker+ 7);
        k20 = __ldg(ker+ 8); k21 = __ldg(ker+ 9); k22 = __ldg(ker+10); k23 = __ldg(ker+11);
        k30 = __ldg(ker+12); k31 = __ldg(ker+13); k32 = __ldg(ker+14); k33 = __ldg(ker+15);
    } else {
        const float b0 = 0.125f, b1 = 0.375f;
        k00=b0*b0; k01=b0*b1; k02=b0*b1; k03=b0*b0;
        k10=b1*b0; k11=b1*b1; k12=b1*b1; k13=b1*b0;
        k20=b1*b0; k21=b1*b1; k22=b1*b1; k23=b1*b0;
        k30=b0*b0; k31=b0*b1; k32=b0*b1; k33=b0*b0;
    }

    const long long idx0 = ((long long)img * HB + i) * WB + lane * 4;
    float4 r0 = make_float4(0.f,0.f,0.f,0.f);
    float4 r1 = make_float4(0.f,0.f,0.f,0.f);
    if (idx0 + 3 < n_in_elems) r0 = *(const float4*)(in + idx0);
    if (i + 1 < HB && idx0 + WB + 3 < n_in_elems) r1 = *(const float4*)(in + idx0 + WB);

    float n0 = __shfl_down_sync(0xffffffffu, r0.x, 1);
    float n1 = __shfl_down_sync(0xffffffffu, r1.x, 1);
    if (lane == 31) { n0 = 0.f; n1 = 0.f; }

    const float ta[5] = { r0.x, r0.y, r0.z, r0.w, n0 };
    const float tb[5] = { r1.x, r1.y, r1.z, r1.w, n1 };

    float ev[8], od[8];
    #pragma unroll
    for (int u = 0; u < 4; ++u) {
        const float A = ta[u], B = ta[u+1], Cv = tb[u], D = tb[u+1];
        ev[2*u+0] = k11*A + k13*B + k31*Cv + k33*D;
        ev[2*u+1] = k10*A + k12*B + k30*Cv + k32*D;
        od[2*u+0] = k01*A + k03*B + k21*Cv + k23*D;
        od[2*u+1] = k00*A + k02*B + k20*Cv + k22*D;
    }

    float* s0 = &sm[w][0][0];
    float* s1 = &sm[w][1][0];
    ((float4*)s0)[2*lane    ] = make_float4(ev[0], ev[1], ev[2], ev[3]);
    ((float4*)s0)[2*lane + 1] = make_float4(ev[4], ev[5], ev[6], ev[7]);
    ((float4*)s1)[2*lane    ] = make_float4(od[0], od[1], od[2], od[3]);
    ((float4*)s1)[2*lane + 1] = make_float4(od[4], od[5], od[6], od[7]);
    __syncwarp();

    const long long obase = (long long)img * OH * OW;
    const long long r0off = obase + (long long)(2*i) * OW;
    const long long r1off = r0off + OW;
    const bool row1_ok = (2*i + 1) < OH;
    #pragma unroll
    for (int u = 0; u < 8; ++u) {
        const int c = lane + 32*u;
        if (c < OW) {
            if (r0off + c < n_out_elems)            out[r0off + c] = s0[c];
            if (row1_ok && r1off + c < n_out_elems) out[r1off + c] = s1[c];
        }
    }
}

extern "C" void kernel_launch(void* const* d_in, const int* in_sizes, int n_in,
                              void* d_out, int out_size)
{
    int imgs_idx = 0;
    for (int j = 1; j < n_in; ++j)
        if (in_sizes[j] > in_sizes[imgs_idx]) imgs_idx = j;
    const float* imgs = (const float*)d_in[imgs_idx];
    const float* ker  = nullptr;
    for (int j = 0; j < n_in; ++j)
        if (j != imgs_idx && in_sizes[j] >= 16 && in_sizes[j] < 1024) { ker = (const float*)d_in[j]; break; }

    const long long n_in_elems = (long long)in_sizes[imgs_idx];

    // Fast path: exact known shapes (2048 planes of 128x128 -> 255x255)
    if (n_in_elems == (long long)2048 * HB * WB &&
        out_size == 2048 * 255 * 255 && ker != nullptr) {
        blur_spec6<<<131072 / 8, 256>>>((const float4*)imgs, (const float4*)ker,
                                        (float*)d_out);
        return;
    }

    const long long planes = n_in_elems / (HB * WB);
    long long per_plane = (planes > 0) ? ((long long)out_size / planes) : 0;
    int ow = (int)(sqrt((double)per_plane) + 0.5);
    if (ow <= 0) ow = 2 * WB - 1;
    const int ntask = (int)(planes * HB);
    blur_generic<<<(ntask + 7) / 8, 256>>>(imgs, ker, (float*)d_out,
                                           ntask, n_in_elems, ow, ow, (long long)out_size);
}

// round 16
// speedup vs baseline: 1.0199x; 1.0199x over previous
#include <cuda_runtime.h>
#include <math.h>

// Blur_22754736735026: upfirdn2d, UP=2, DOWN=1, 4x4 kernel, pad (1,2).
// imgs: (16,128,128,128) f32 NCHW -> out: (16,128,255,255) f32.
//
// out(2i+py, 2j+px) = 2x2 weighted sum of in(i..i+1, j..j+1):
//   even out rows: kernel rows 1,3 ; odd rows: kernel rows 0,2
//   even out cols: kernel cols 1,3 ; odd cols: kernel cols 0,2
// Odd output row 2i+1 exists iff i < 127 (OH=255).
//
// FINAL (confirmed over 15 rounds): warp task = 2 input rows (3 front-batched
// LDG.128), two smem-staged pairs (STS.128), coalesced scalar __stcs drain
// (pitch 255 forbids vector stores), __launch_bounds__(256, 7).
// Best measured: 103.5 us bench / 101.4 us ncu, DRAM ~75%, ~5.95 TB/s —
// at the write-dominant HBM wall (compulsory traffic ~667 MB logical).

#define HB   128
#define WB   128

// ---------------- specialized: shapes known -----------
__global__ __launch_bounds__(256, 7)
void blur_spec6(const float4* __restrict__ in4,
                const float4* __restrict__ ker4,
                float* __restrict__ out)
{
    __shared__ float sm[8][2][256];

    const int lane = threadIdx.x & 31;
    const int w    = threadIdx.x >> 5;
    const unsigned task = blockIdx.x * 8u + w;     // 131072 tasks
    const unsigned t    = task & 63u;              // row-pair index in plane
    const unsigned img  = task >> 6;
    const unsigned i0   = 2u * t;

    float kw[16];
    {
        const float4 a = __ldg(ker4 + 0), b = __ldg(ker4 + 1),
                     c = __ldg(ker4 + 2), d = __ldg(ker4 + 3);
        kw[ 0]=a.x; kw[ 1]=a.y; kw[ 2]=a.z; kw[ 3]=a.w;
        kw[ 4]=b.x; kw[ 5]=b.y; kw[ 6]=b.z; kw[ 7]=b.w;
        kw[ 8]=c.x; kw[ 9]=c.y; kw[10]=c.z; kw[11]=c.w;
        kw[12]=d.x; kw[13]=d.y; kw[14]=d.z; kw[15]=d.w;
    }

    const unsigned rowbase = (img * HB + i0) * 32u + lane;
    const bool lastpair = (t == 63u);              // warp-uniform

    float4 r0 = in4[rowbase];
    float4 r1 = in4[rowbase + 32u];
    float4 r2 = make_float4(0.f, 0.f, 0.f, 0.f);
    if (!lastpair) r2 = in4[rowbase + 64u];

    float n0 = __shfl_down_sync(0xffffffffu, r0.x, 1);
    float n1 = __shfl_down_sync(0xffffffffu, r1.x, 1);
    float n2 = __shfl_down_sync(0xffffffffu, r2.x, 1);
    if (lane == 31) { n0 = 0.f; n1 = 0.f; n2 = 0.f; }

    float* s0 = &sm[w][0][0];
    float* s1 = &sm[w][1][0];
    const unsigned g0A = img * 65025u + i0 * 510u;

    // ---- pair A: rows i0,i0+1 -> out rows 2i0, 2i0+1 (both exist) ----
    {
        const float ta[5] = { r0.x, r0.y, r0.z, r0.w, n0 };
        const float tb[5] = { r1.x, r1.y, r1.z, r1.w, n1 };
        float ev[8], od[8];
        #pragma unroll
        for (int u = 0; u < 4; ++u) {
            const float A = ta[u], B = ta[u+1], Cv = tb[u], D = tb[u+1];
            ev[2*u+0] = kw[5]*A + kw[7]*B + kw[13]*Cv + kw[15]*D;
            ev[2*u+1] = kw[4]*A + kw[6]*B + kw[12]*Cv + kw[14]*D;
            od[2*u+0] = kw[1]*A + kw[3]*B + kw[ 9]*Cv + kw[11]*D;
            od[2*u+1] = kw[0]*A + kw[2]*B + kw[ 8]*Cv + kw[10]*D;
        }
        ((float4*)s0)[2*lane    ] = make_float4(ev[0], ev[1], ev[2], ev[3]);
        ((float4*)s0)[2*lane + 1] = make_float4(ev[4], ev[5], ev[6], ev[7]);
        ((float4*)s1)[2*lane    ] = make_float4(od[0], od[1], od[2], od[3]);
        ((float4*)s1)[2*lane + 1] = make_float4(od[4], od[5], od[6], od[7]);
        __syncwarp();

        const unsigned o0 = g0A;
        const unsigned o1 = g0A + 255u;
        #pragma unroll
        for (int u = 0; u < 8; ++u) {
            const int c = lane + 32*u;
            if (u < 7 || lane < 31) {              // c < 255
                __stcs(out + o0 + c, s0[c]);
                __stcs(out + o1 + c, s1[c]);
            }
        }
        __syncwarp();                              // WAR: drain A before stage B
    }

    // ---- pair B: rows i0+1,i0+2 -> out rows 2i0+2, 2i0+3 ----
    {
        const float ta[5] = { r1.x, r1.y, r1.z, r1.w, n1 };
        const float tb[5] = { r2.x, r2.y, r2.z, r2.w, n2 };
        float ev[8], od[8];
        #pragma unroll
        for (int u = 0; u < 4; ++u) {
            const float A = ta[u], B = ta[u+1], Cv = tb[u], D = tb[u+1];
            ev[2*u+0] = kw[5]*A + kw[7]*B + kw[13]*Cv + kw[15]*D;
            ev[2*u+1] = kw[4]*A + kw[6]*B + kw[12]*Cv + kw[14]*D;
            od[2*u+0] = kw[1]*A + kw[3]*B + kw[ 9]*Cv + kw[11]*D;
            od[2*u+1] = kw[0]*A + kw[2]*B + kw[ 8]*Cv + kw[10]*D;
        }
        ((float4*)s0)[2*lane    ] = make_float4(ev[0], ev[1], ev[2], ev[3]);
        ((float4*)s0)[2*lane + 1] = make_float4(ev[4], ev[5], ev[6], ev[7]);
        ((float4*)s1)[2*lane    ] = make_float4(od[0], od[1], od[2], od[3]);
        ((float4*)s1)[2*lane + 1] = make_float4(od[4], od[5], od[6], od[7]);
        __syncwarp();

        const unsigned o0 = g0A + 510u;
        const unsigned o1 = o0 + 255u;
        #pragma unroll
        for (int u = 0; u < 8; ++u) {
            const int c = lane + 32*u;
            if (u < 7 || lane < 31) {              // c < 255
                __stcs(out + o0 + c, s0[c]);
                if (!lastpair) __stcs(out + o1 + c, s1[c]);
            }
        }
    }
}

// ---------------- generic guarded fallback (any shape) ----------------------
__global__ __launch_bounds__(256)
void blur_generic(const float* __restrict__ in,
                  const float* __restrict__ ker,
                  float* __restrict__ out,
                  int ntask, long long n_in_elems,
                  int OH, int OW, long long n_out_elems)
{
    __shared__ float sm[8][2][256];

    const int lane = threadIdx.x & 31;
    const int w    = threadIdx.x >> 5;
    const int task = blockIdx.x * 8 + w;
    if (task >= ntask) return;
    const int i    = task & (HB - 1);
    const int img  = task >> 7;

    float k00,k01,k02,k03,k10,k11,k12,k13,k20,k21,k22,k23,k30,k31,k32,k33;
    if (ker != nullptr) {
        k00 = __ldg(ker+ 0); k01 = __ldg(ker+ 1); k02 = __ldg(ker+ 2); k03 = __ldg(ker+ 3);
        k10 = __ldg(ker+ 4); k11 = __ldg(ker+ 5); k12 = __ldg(ker+ 6); k13 = __ldg(ker+ 7);
        k20 = __ldg(ker+ 8); k21 = __ldg(ker+ 9); k22 = __ldg(ker+10); k23 = __ldg(ker+11);
        k30 = __ldg(ker+12); k31 = __ldg(ker+13); k32 = __ldg(ker+14); k33 = __ldg(ker+15);
    } else {
        const float b0 = 0.125f, b1 = 0.375f;
        k00=b0*b0; k01=b0*b1; k02=b0*b1; k03=b0*b0;
        k10=b1*b0; k11=b1*b1; k12=b1*b1; k13=b1*b0;
        k20=b1*b0; k21=b1*b1; k22=b1*b1; k23=b1*b0;
        k30=b0*b0; k31=b0*b1; k32=b0*b1; k33=b0*b0;
    }

    const long long idx0 = ((long long)img * HB + i) * WB + lane * 4;
    float4 r0 = make_float4(0.f,0.f,0.f,0.f);
    float4 r1 = make_float4(0.f,0.f,0.f,0.f);
    if (idx0 + 3 < n_in_elems) r0 = *(const float4*)(in + idx0);
    if (i + 1 < HB && idx0 + WB + 3 < n_in_elems) r1 = *(const float4*)(in + idx0 + WB);

    float n0 = __shfl_down_sync(0xffffffffu, r0.x, 1);
    float n1 = __shfl_down_sync(0xffffffffu, r1.x, 1);
    if (lane == 31) { n0 = 0.f; n1 = 0.f; }

    const float ta[5] = { r0.x, r0.y, r0.z, r0.w, n0 };
    const float tb[5] = { r1.x, r1.y, r1.z, r1.w, n1 };

    float ev[8], od[8];
    #pragma unroll
    for (int u = 0; u < 4; ++u) {
        const float A = ta[u], B = ta[u+1], Cv = tb[u], D = tb[u+1];
        ev[2*u+0] = k11*A + k13*B + k31*Cv + k33*D;
        ev[2*u+1] = k10*A + k12*B + k30*Cv + k32*D;
        od[2*u+0] = k01*A + k03*B + k21*Cv + k23*D;
        od[2*u+1] = k00*A + k02*B + k20*Cv + k22*D;
    }

    float* s0 = &sm[w][0][0];
    float* s1 = &sm[w][1][0];
    ((float4*)s0)[2*lane    ] = make_float4(ev[0], ev[1], ev[2], ev[3]);
    ((float4*)s0)[2*lane + 1] = make_float4(ev[4], ev[5], ev[6], ev[7]);
    ((float4*)s1)[2*lane    ] = make_float4(od[0], od[1], od[2], od[3]);
    ((float4*)s1)[2*lane + 1] = make_float4(od[4], od[5], od[6], od[7]);
    __syncwarp();

    const long long obase = (long long)img * OH * OW;
    const long long r0off = obase + (long long)(2*i) * OW;
    const long long r1off = r0off + OW;
    const bool row1_ok = (2*i + 1) < OH;
    #pragma unroll
    for (int u = 0; u < 8; ++u) {
        const int c = lane + 32*u;
        if (c < OW) {
            if (r0off + c < n_out_elems)            out[r0off + c] = s0[c];
            if (row1_ok && r1off + c < n_out_elems) out[r1off + c] = s1[c];
        }
    }
}

extern "C" void kernel_launch(void* const* d_in, const int* in_sizes, int n_in,
                              void* d_out, int out_size)
{
    int imgs_idx = 0;
    for (int j = 1; j < n_in; ++j)
        if (in_sizes[j] > in_sizes[imgs_idx]) imgs_idx = j;
    const float* imgs = (const float*)d_in[imgs_idx];
    const float* ker  = nullptr;
    for (int j = 0; j < n_in; ++j)
        if (j != imgs_idx && in_sizes[j] >= 16 && in_sizes[j] < 1024) { ker = (const float*)d_in[j]; break; }

    const long long n_in_elems = (long long)in_sizes[imgs_idx];

    // Fast path: exact known shapes (2048 planes of 128x128 -> 255x255)
    if (n_in_elems == (long long)2048 * HB * WB &&
        out_size == 2048 * 255 * 255 && ker != nullptr) {
        blur_spec6<<<131072 / 8, 256>>>((const float4*)imgs, (const float4*)ker,
                                        (float*)d_out);
        return;
    }

    const long long planes = n_in_elems / (HB * WB);
    long long per_plane = (planes > 0) ? ((long long)out_size / planes) : 0;
    int ow = (int)(sqrt((double)per_plane) + 0.5);
    if (ow <= 0) ow = 2 * WB - 1;
    const int ntask = (int)(planes * HB);
    blur_generic<<<(ntask + 7) / 8, 256>>>(imgs, ker, (float*)d_out,
                                           ntask, n_in_elems, ow, ow, (long long)out_size);
}